// round 2
// baseline (speedup 1.0000x reference)
#include <cuda_runtime.h>
#include <math.h>

#define N_NODES 8192

// Per-row inverse normalizer scratch (no cudaMalloc allowed).
__device__ float g_row_inv[N_NODES];

// ---------------------------------------------------------------------------
// Kernel 1: zero the row-sum accumulator
// ---------------------------------------------------------------------------
__global__ void k_rowsum_init() {
    int i = blockIdx.x * blockDim.x + threadIdx.x;
    if (i < N_NODES) g_row_inv[i] = 0.0f;
}

// ---------------------------------------------------------------------------
// Kernel 2: accumulate per-row sums from both edge lists (scaled by alpha /
// 1-alpha). One thread per edge slot across both lists.
// ---------------------------------------------------------------------------
__global__ void k_rowsum(const int* __restrict__ rows_s,
                         const float* __restrict__ vals_s,
                         const int* __restrict__ rows_t,
                         const float* __restrict__ vals_t,
                         const float* __restrict__ gamma,
                         int E) {
    int i = blockIdx.x * blockDim.x + threadIdx.x;
    float alpha = 1.0f / (1.0f + expf(-gamma[0]));
    if (i < E) {
        atomicAdd(&g_row_inv[rows_s[i]], alpha * vals_s[i]);
    } else if (i < 2 * E) {
        int j = i - E;
        atomicAdd(&g_row_inv[rows_t[j]], (1.0f - alpha) * vals_t[j]);
    }
}

// ---------------------------------------------------------------------------
// Kernel 3: convert sums to inverses (rows with sum==0 get divisor 1.0)
// ---------------------------------------------------------------------------
__global__ void k_rowsum_invert() {
    int i = blockIdx.x * blockDim.x + threadIdx.x;
    if (i < N_NODES) {
        float s = g_row_inv[i];
        g_row_inv[i] = (s == 0.0f) ? 1.0f : (1.0f / s);
    }
}

// ---------------------------------------------------------------------------
// Kernel 4: zero-fill the 256 MB dense output (float4-vectorized)
// ---------------------------------------------------------------------------
__global__ void k_zero_out(float4* __restrict__ out, long long n4) {
    long long i = (long long)blockIdx.x * blockDim.x + threadIdx.x;
    if (i < n4) out[i] = make_float4(0.f, 0.f, 0.f, 0.f);
}

// ---------------------------------------------------------------------------
// Kernel 5: scatter normalized scaled values into the dense output.
// Pre-divide by the row sum so no full-matrix normalization pass is needed.
// ---------------------------------------------------------------------------
__global__ void k_scatter(const int* __restrict__ rows_s,
                          const int* __restrict__ cols_s,
                          const float* __restrict__ vals_s,
                          const int* __restrict__ rows_t,
                          const int* __restrict__ cols_t,
                          const float* __restrict__ vals_t,
                          const float* __restrict__ gamma,
                          float* __restrict__ out,
                          int E) {
    int i = blockIdx.x * blockDim.x + threadIdx.x;
    float alpha = 1.0f / (1.0f + expf(-gamma[0]));
    if (i < E) {
        int r = rows_s[i];
        int c = cols_s[i];
        float v = alpha * vals_s[i] * g_row_inv[r];
        atomicAdd(&out[(long long)r * N_NODES + c], v);
    } else if (i < 2 * E) {
        int j = i - E;
        int r = rows_t[j];
        int c = cols_t[j];
        float v = (1.0f - alpha) * vals_t[j] * g_row_inv[r];
        atomicAdd(&out[(long long)r * N_NODES + c], v);
    }
}

// ---------------------------------------------------------------------------
// Launcher
// ---------------------------------------------------------------------------
extern "C" void kernel_launch(void* const* d_in, const int* in_sizes, int n_in,
                              void* d_out, int out_size) {
    const int*   rows_s = (const int*)d_in[0];
    const int*   cols_s = (const int*)d_in[1];
    const float* vals_s = (const float*)d_in[2];
    const int*   rows_t = (const int*)d_in[3];
    const int*   cols_t = (const int*)d_in[4];
    const float* vals_t = (const float*)d_in[5];
    const float* gamma  = (const float*)d_in[6];
    float* out = (float*)d_out;

    const int E = in_sizes[0];

    // 1) row-sum pipeline (small)
    k_rowsum_init<<<(N_NODES + 255) / 256, 256>>>();
    {
        int total = 2 * E;
        k_rowsum<<<(total + 255) / 256, 256>>>(rows_s, vals_s, rows_t, vals_t,
                                               gamma, E);
    }
    k_rowsum_invert<<<(N_NODES + 255) / 256, 256>>>();

    // 2) zero the dense output (the traffic-dominant pass)
    {
        long long n4 = (long long)out_size / 4;  // 64M floats -> 16M float4
        long long blocks = (n4 + 255) / 256;
        k_zero_out<<<(unsigned)blocks, 256>>>((float4*)out, n4);
    }

    // 3) scatter pre-normalized values
    {
        int total = 2 * E;
        k_scatter<<<(total + 255) / 256, 256>>>(rows_s, cols_s, vals_s,
                                                rows_t, cols_t, vals_t,
                                                gamma, out, E);
    }
}